// round 2
// baseline (speedup 1.0000x reference)
#include <cuda_runtime.h>

#define D 768
#define MAX_ROWS 32768
#define MAX_CODES 8192
#define EPSF 1e-6f

#define BM 128
#define BN 128
#define BK 16
#define LDPAD 4          // smem row pad
#define SROW (BM + LDPAD)

// ---------------- device scratch (no allocations allowed) ----------------
__device__ float g_en2[MAX_CODES];
__device__ int   g_idx[MAX_ROWS];
__device__ float g_partial[MAX_ROWS / 8];

// ---------------- kernel 1: per-code squared norms ----------------
__global__ void k_en2(const float* __restrict__ emb, int ncodes) {
    int code = blockIdx.x * 8 + (threadIdx.x >> 5);
    int lane = threadIdx.x & 31;
    if (code >= ncodes) return;
    const float* e = emb + (size_t)code * D;
    float s = 0.f;
#pragma unroll
    for (int j = 0; j < D / 32; j++) {
        float v = e[lane + 32 * j];
        s = fmaf(v, v, s);
    }
#pragma unroll
    for (int o = 16; o; o >>= 1) s += __shfl_xor_sync(0xffffffffu, s, o);
    if (lane == 0) g_en2[code] = s;
}

// ---------------- kernel 2: distance GEMM + argmin ----------------
// d(m,n) = ||e_n||^2 - 2 * z_m . e_n   (||z_m||^2 constant per row -> dropped)
// 256 threads, 128x128 tile, 8x8 register blocking, BK=16.
__global__ __launch_bounds__(256, 2)
void k_dist(const float* __restrict__ z, const float* __restrict__ emb, int ncodes) {
    __shared__ float As[BK][SROW];   // z^T tile: As[k][m]
    __shared__ float Bs[BK][SROW];   // e^T tile: Bs[k][n]
    __shared__ float s_val[16][BM];
    __shared__ int   s_idx[16][BM];

    const int tid = threadIdx.x;
    const int tx = tid & 15;        // column-thread
    const int ty = tid >> 4;        // row-thread
    const int m0 = blockIdx.x * BM;

    float best[8];
    int   bidx[8];
#pragma unroll
    for (int i = 0; i < 8; i++) { best[i] = 3.4e38f; bidx[i] = 0; }

    for (int n0 = 0; n0 < ncodes; n0 += BN) {
        float acc[8][8];
#pragma unroll
        for (int i = 0; i < 8; i++)
#pragma unroll
            for (int j = 0; j < 8; j++) acc[i][j] = 0.f;

        for (int k0 = 0; k0 < D; k0 += BK) {
            // cooperative load: 128 rows x 16 k for both tiles (float4 each)
#pragma unroll
            for (int q = 0; q < 2; q++) {
                int u = tid + q * 256;      // 0..511
                int r = u >> 2;             // 0..127
                int c = (u & 3) * 4;        // 0,4,8,12
                float4 va = *(const float4*)(z   + (size_t)(m0 + r) * D + k0 + c);
                As[c + 0][r] = va.x; As[c + 1][r] = va.y;
                As[c + 2][r] = va.z; As[c + 3][r] = va.w;
                float4 vb = *(const float4*)(emb + (size_t)(n0 + r) * D + k0 + c);
                Bs[c + 0][r] = vb.x; Bs[c + 1][r] = vb.y;
                Bs[c + 2][r] = vb.z; Bs[c + 3][r] = vb.w;
            }
            __syncthreads();
#pragma unroll
            for (int kk = 0; kk < BK; kk++) {
                float a[8], b[8];
#pragma unroll
                for (int i = 0; i < 8; i++) a[i] = As[kk][ty + 16 * i];  // broadcast
#pragma unroll
                for (int j = 0; j < 8; j++) b[j] = Bs[kk][tx + 16 * j];  // conflict-free
#pragma unroll
                for (int i = 0; i < 8; i++)
#pragma unroll
                    for (int j = 0; j < 8; j++) acc[i][j] = fmaf(a[i], b[j], acc[i][j]);
            }
            __syncthreads();
        }

        // fold this 128-code tile into the running per-row argmin
#pragma unroll
        for (int j = 0; j < 8; j++) {
            int n = n0 + tx + 16 * j;
            float en2 = __ldg(&g_en2[n]);
#pragma unroll
            for (int i = 0; i < 8; i++) {
                float dist = fmaf(-2.f, acc[i][j], en2);
                if (dist < best[i] || (dist == best[i] && n < bidx[i])) {
                    best[i] = dist; bidx[i] = n;
                }
            }
        }
    }

    // reduce across the 16 column-threads sharing each row
#pragma unroll
    for (int i = 0; i < 8; i++) {
        s_val[tx][ty + 16 * i] = best[i];
        s_idx[tx][ty + 16 * i] = bidx[i];
    }
    __syncthreads();
    if (tid < BM) {
        float bv = s_val[0][tid];
        int   bi = s_idx[0][tid];
#pragma unroll
        for (int t = 1; t < 16; t++) {
            float v = s_val[t][tid];
            int   ix = s_idx[t][tid];
            if (v < bv || (v == bv && ix < bi)) { bv = v; bi = ix; }
        }
        g_idx[m0 + tid] = bi;
    }
}

// ---------------- kernel 3: rotation-trick epilogue + loss partials ----------------
// rotated = A*z + B*e, with A,B closed-form from (zz, ee, ze).
__global__ void k_rotate(const float* __restrict__ z, const float* __restrict__ emb,
                         float* __restrict__ out, int nrows) {
    __shared__ float s_loss[8];
    int warp = threadIdx.x >> 5;
    int lane = threadIdx.x & 31;
    int row = blockIdx.x * 8 + warp;
    float loss_w = 0.f;

    if (row < nrows) {
        const float* zr = z + (size_t)row * D;
        const float* er = emb + (size_t)g_idx[row] * D;
        float zv[D / 32], ev[D / 32];
        float zz = 0.f, ee = 0.f, ze = 0.f;
#pragma unroll
        for (int j = 0; j < D / 32; j++) {
            zv[j] = zr[lane + 32 * j];
            ev[j] = er[lane + 32 * j];
            zz = fmaf(zv[j], zv[j], zz);
            ee = fmaf(ev[j], ev[j], ee);
            ze = fmaf(zv[j], ev[j], ze);
        }
#pragma unroll
        for (int o = 16; o; o >>= 1) {
            zz += __shfl_xor_sync(0xffffffffu, zz, o);
            ee += __shfl_xor_sync(0xffffffffu, ee, o);
            ze += __shfl_xor_sync(0xffffffffu, ze, o);
        }
        float ns_r = sqrtf(zz), nt_r = sqrtf(ee);
        float ns = fmaxf(ns_r, EPSF), nt = fmaxf(nt_r, EPSF);
        float dot_eu = zz / ns;                               // z . u
        float w2 = zz / (ns * ns) + ee / (nt * nt) + 2.f * ze / (ns * nt);
        float nw = fmaxf(sqrtf(w2), EPSF);
        float dot_ew = (dot_eu + ze / nt) / nw;               // z . w
        float scale = nt_r / ns;                              // norm_tgt / max(norm_src,eps)
        float A = scale * (1.f - 2.f * dot_ew / (ns * nw));
        float B = scale * 2.f * (dot_eu - dot_ew / nw) / nt;

        float* orow = out + (size_t)row * D;
#pragma unroll
        for (int j = 0; j < D / 32; j++)
            orow[lane + 32 * j] = fmaf(A, zv[j], B * ev[j]);

        loss_w = zz + ee - 2.f * ze;   // sum (e - z)^2 for this row
    }

    // deterministic per-block partial (warp lanes already hold full-row sums)
    if (lane == 0) s_loss[warp] = loss_w;
    __syncthreads();
    if (threadIdx.x == 0) {
        float s = 0.f;
#pragma unroll
        for (int w = 0; w < 8; w++) s += s_loss[w];
        g_partial[blockIdx.x] = s;
    }
}

// ---------------- kernel 4: finalize scalar loss ----------------
__global__ void k_loss(float* __restrict__ out, int nparts, float inv_count, long long pos) {
    __shared__ float sm[256];
    float s = 0.f;
    for (int i = threadIdx.x; i < nparts; i += 256) s += g_partial[i];
    sm[threadIdx.x] = s;
    __syncthreads();
    for (int o = 128; o; o >>= 1) {
        if (threadIdx.x < o) sm[threadIdx.x] += sm[threadIdx.x + o];
        __syncthreads();
    }
    if (threadIdx.x == 0) out[pos] = 2.f * sm[0] * inv_count;
}

// ---------------- launch ----------------
extern "C" void kernel_launch(void* const* d_in, const int* in_sizes, int n_in,
                              void* d_out, int out_size) {
    const float* z   = (const float*)d_in[0];
    const float* emb = (const float*)d_in[1];
    float* out = (float*)d_out;

    int nrows  = in_sizes[0] / D;    // 32768
    int ncodes = in_sizes[1] / D;    // 8192

    k_en2<<<(ncodes + 7) / 8, 256>>>(emb, ncodes);
    k_dist<<<nrows / BM, 256>>>(z, emb, ncodes);
    k_rotate<<<nrows / 8, 256>>>(z, emb, out, nrows);

    long long zq_elems = (long long)nrows * D;
    long long loss_pos = (out_size > zq_elems) ? zq_elems : (long long)out_size - 1;
    k_loss<<<1, 256>>>(out, nrows / 8, 1.f / ((float)nrows * (float)D), loss_pos);
}

// round 6
// speedup vs baseline: 2.7586x; 2.7586x over previous
#include <cuda_runtime.h>
#include <cstdint>

#define D 768
#define NROWS 32768
#define NCODES 8192
#define EPSF 1e-6f

// ---- GEMM tiling ----
#define CTAM 256
#define CTAN 128
#define KCH 8                  // floats per k-chunk = one m16n8k8 step
#define NCHUNK (D / KCH)       // 96
#define NITER (NCODES / CTAN)  // 64
#define PADK 12                // smem row stride (floats); l4*12+lc mod 32 all-distinct
#define NCAND 16               // 8 contributing threads per row x top-2 each

// ---------------- device scratch (no allocations allowed) ----------------
__device__ __align__(256) float g_Zh[NROWS * D];   // tf32-rounded z
__device__ __align__(256) float g_Eh[NCODES * D];  // tf32-rounded emb
__device__ float g_en2[NCODES];
__device__ int   g_cand[NROWS * NCAND];
__device__ float g_partial[NROWS / 8];

// ---------------- helpers ----------------
__device__ __forceinline__ uint32_t smem_u32(const void* p) {
    uint32_t a;
    asm("{ .reg .u64 t; cvta.to.shared.u64 t, %1; cvt.u32.u64 %0, t; }" : "=r"(a) : "l"(p));
    return a;
}
__device__ __forceinline__ void cp16(uint32_t dst, const float* src) {
    asm volatile("cp.async.cg.shared.global [%0], [%1], 16;" :: "r"(dst), "l"(src));
}
#define CP_COMMIT() asm volatile("cp.async.commit_group;")
#define CP_WAIT1()  asm volatile("cp.async.wait_group 1;")
#define CP_WAIT0()  asm volatile("cp.async.wait_group 0;")

__device__ __forceinline__ float tf32_rna(float x) {
    uint32_t r;
    asm("cvt.rna.tf32.f32 %0, %1;" : "=r"(r) : "f"(x));
    return __uint_as_float(r);
}
__device__ __forceinline__ void mma_tf32(float* c, const uint32_t* a, const uint32_t* b) {
    asm volatile(
        "mma.sync.aligned.m16n8k8.row.col.f32.tf32.tf32.f32 "
        "{%0,%1,%2,%3}, {%4,%5,%6,%7}, {%8,%9}, {%0,%1,%2,%3};"
        : "+f"(c[0]), "+f"(c[1]), "+f"(c[2]), "+f"(c[3])
        : "r"(a[0]), "r"(a[1]), "r"(a[2]), "r"(a[3]), "r"(b[0]), "r"(b[1]));
}

// ---------------- kernel 0: tf32 rounding of both operands ----------------
__global__ void k_split(const float4* __restrict__ z, const float4* __restrict__ e,
                        int nz4, int ne4) {
    float4* zh = (float4*)g_Zh;
    float4* eh = (float4*)g_Eh;
    for (int i = blockIdx.x * blockDim.x + threadIdx.x; i < nz4; i += gridDim.x * blockDim.x) {
        float4 v = z[i];
        float4 h;
        h.x = tf32_rna(v.x); h.y = tf32_rna(v.y);
        h.z = tf32_rna(v.z); h.w = tf32_rna(v.w);
        zh[i] = h;
        if (i < ne4) {
            float4 w = e[i];
            float4 he;
            he.x = tf32_rna(w.x); he.y = tf32_rna(w.y);
            he.z = tf32_rna(w.z); he.w = tf32_rna(w.w);
            eh[i] = he;
        }
    }
}

// ---------------- kernel 1: per-code squared norms (exact fp32) ----------------
__global__ void k_en2(const float* __restrict__ emb, int ncodes) {
    int code = blockIdx.x * 8 + (threadIdx.x >> 5);
    int lane = threadIdx.x & 31;
    if (code >= ncodes) return;
    const float* e = emb + (size_t)code * D;
    float s = 0.f;
#pragma unroll
    for (int j = 0; j < D / 32; j++) { float v = e[lane + 32 * j]; s = fmaf(v, v, s); }
#pragma unroll
    for (int o = 16; o; o >>= 1) s += __shfl_xor_sync(0xffffffffu, s, o);
    if (lane == 0) g_en2[code] = s;
}

// ---------------- kernel 2: tf32 mma.sync distance GEMM + top-2 candidates ----------------
// approx dist(m,n) = ||e_n||^2 - 2 * zh_m . eh_n   (||z||^2 constant per row -> dropped)
__global__ __launch_bounds__(256, 1)
void k_gemm() {
    __shared__ float sA[2][CTAM * PADK];   // 2 x 12288 B
    __shared__ float sB[2][CTAN * PADK];   // 2 x  6144 B
    __shared__ float sEn2[CTAN];

    const int tid = threadIdx.x;
    const int wid = tid >> 5;
    const int lane = tid & 31;
    const int m0 = blockIdx.x * CTAM;
    const int wm = (wid & 3) * 64;   // warp M offset
    const int nh = wid >> 2;         // N-half 0/1
    const int wn = nh * 64;          // warp N offset
    const int l4 = lane >> 2;        // groupID 0..7
    const int lc = lane & 3;         // tid-in-group 0..3

    const float* gZ = g_Zh;
    const float* gE = g_Eh;

    const uint32_t sa0 = smem_u32(&sA[0][0]);
    const uint32_t sa1 = smem_u32(&sA[1][0]);
    const uint32_t sb0 = smem_u32(&sB[0][0]);
    const uint32_t sb1 = smem_u32(&sB[1][0]);

    const int arow0 = tid >> 1, aseg = (tid & 1) * 4;
    const int brow  = tid >> 1, bseg = (tid & 1) * 4;

    // candidate lists: 8 rows per thread (4 m-tiles x 2 halves), top-2 each
    float cv0[8], cv1[8];
    int   ci0[8], ci1[8];
#pragma unroll
    for (int r = 0; r < 8; r++) { cv0[r] = 3.4e38f; cv1[r] = 3.4e38f; ci0[r] = 0; ci1[r] = 0; }

    const int aoff = (wm + l4) * PADK + lc;
    const int boff = (wn + l4) * PADK + lc;

    for (int it = 0; it < NITER; it++) {
        const int n0 = it * CTAN;
        __syncthreads();                    // prev iter fully consumed (smem + sEn2)
        if (tid < CTAN) sEn2[tid] = g_en2[n0 + tid];

        // prologue: chunk 0 -> stage 0
        {
            cp16(sa0 + arow0 * (PADK * 4) + aseg * 4, gZ + (size_t)(m0 + arow0) * D + aseg);
            cp16(sa0 + (arow0 + 128) * (PADK * 4) + aseg * 4,
                 gZ + (size_t)(m0 + arow0 + 128) * D + aseg);
            cp16(sb0 + brow * (PADK * 4) + bseg * 4, gE + (size_t)(n0 + brow) * D + bseg);
            CP_COMMIT();
        }

        float acc[4][8][4];
#pragma unroll
        for (int mt = 0; mt < 4; mt++)
#pragma unroll
            for (int nt = 0; nt < 8; nt++)
#pragma unroll
                for (int q = 0; q < 4; q++) acc[mt][nt][q] = 0.f;

        for (int c = 0; c < NCHUNK; c++) {
            const uint32_t sa_nxt = ((c + 1) & 1) ? sa1 : sa0;
            const uint32_t sb_nxt = ((c + 1) & 1) ? sb1 : sb0;
            __syncthreads();                // next stage's previous readers done
            if (c + 1 < NCHUNK) {
                const int kc = (c + 1) * KCH;
                cp16(sa_nxt + arow0 * (PADK * 4) + aseg * 4,
                     gZ + (size_t)(m0 + arow0) * D + kc + aseg);
                cp16(sa_nxt + (arow0 + 128) * (PADK * 4) + aseg * 4,
                     gZ + (size_t)(m0 + arow0 + 128) * D + kc + aseg);
                cp16(sb_nxt + brow * (PADK * 4) + bseg * 4,
                     gE + (size_t)(n0 + brow) * D + kc + bseg);
                CP_COMMIT();
                CP_WAIT1();                 // chunk c landed
            } else {
                CP_WAIT0();
            }
            __syncthreads();                // chunk c visible CTA-wide

            const float* As = sA[c & 1];
            const float* Bs = sB[c & 1];
            uint32_t af[4][4], bf[8][2];
#pragma unroll
            for (int mt = 0; mt < 4; mt++) {
                int b = aoff + mt * (16 * PADK);
                af[mt][0] = __float_as_uint(As[b]);
                af[mt][1] = __float_as_uint(As[b + 8 * PADK]);
                af[mt][2] = __float_as_uint(As[b + 4]);
                af[mt][3] = __float_as_uint(As[b + 8 * PADK + 4]);
            }
#pragma unroll
            for (int nt = 0; nt < 8; nt++) {
                int b = boff + nt * (8 * PADK);
                bf[nt][0] = __float_as_uint(Bs[b]);
                bf[nt][1] = __float_as_uint(Bs[b + 4]);
            }
#pragma unroll
            for (int mt = 0; mt < 4; mt++)
#pragma unroll
                for (int nt = 0; nt < 8; nt++)
                    mma_tf32(acc[mt][nt], af[mt], bf[nt]);
        }

        // ---- fold this 128-code tile into per-row top-2 ----
#pragma unroll
        for (int mt = 0; mt < 4; mt++) {
#pragma unroll
            for (int h = 0; h < 2; h++) {
                const int r = mt * 2 + h;
#pragma unroll
                for (int nt = 0; nt < 8; nt++) {
#pragma unroll
                    for (int q = 0; q < 2; q++) {
                        int nl = wn + nt * 8 + 2 * lc + q;
                        float dist = fmaf(-2.f, acc[mt][nt][h * 2 + q], sEn2[nl]);
                        int n = n0 + nl;
                        if (dist < cv1[r]) {
                            if (dist < cv0[r]) {
                                cv1[r] = cv0[r]; ci1[r] = ci0[r];
                                cv0[r] = dist;   ci0[r] = n;
                            } else {
                                cv1[r] = dist;   ci1[r] = n;
                            }
                        }
                    }
                }
            }
        }
    }

    // ---- write candidates: 16 per row; slot = n_half*8 + lc*2 (+1) -> no collisions ----
#pragma unroll
    for (int mt = 0; mt < 4; mt++) {
#pragma unroll
        for (int h = 0; h < 2; h++) {
            int r = mt * 2 + h;
            int grow = m0 + wm + mt * 16 + l4 + h * 8;
            int slot = nh * 8 + lc * 2;
            g_cand[(size_t)grow * NCAND + slot + 0] = ci0[r];
            g_cand[(size_t)grow * NCAND + slot + 1] = ci1[r];
        }
    }
}

// ---------------- kernel 3: exact rescore + rotation + loss partials ----------------
__global__ void k_rotate(const float* __restrict__ z, const float* __restrict__ emb,
                         float* __restrict__ out, int nrows) {
    __shared__ float s_loss[8];
    int warp = threadIdx.x >> 5;
    int lane = threadIdx.x & 31;
    int row = blockIdx.x * 8 + warp;
    float loss_w = 0.f;

    if (row < nrows) {
        const float* zr = z + (size_t)row * D;
        float zv[D / 32];
        float zz = 0.f;
#pragma unroll
        for (int j = 0; j < D / 32; j++) {
            zv[j] = zr[lane + 32 * j];
            zz = fmaf(zv[j], zv[j], zz);
        }
#pragma unroll
        for (int o = 16; o; o >>= 1) zz += __shfl_xor_sync(0xffffffffu, zz, o);

        // exact rescore of 16 candidates
        float best_key = 3.4e38f;
        int best_i = 0x7fffffff;
#pragma unroll
        for (int c = 0; c < NCAND; c++) {
            int ci = g_cand[(size_t)row * NCAND + c] & (NCODES - 1);  // fault guard
            const float* er = emb + (size_t)ci * D;
            float ze = 0.f;
#pragma unroll
            for (int j = 0; j < D / 32; j++) ze = fmaf(zv[j], er[lane + 32 * j], ze);
#pragma unroll
            for (int o = 16; o; o >>= 1) ze += __shfl_xor_sync(0xffffffffu, ze, o);
            float key = fmaf(-2.f, ze, g_en2[ci]);
            if (key < best_key || (key == best_key && ci < best_i)) { best_key = key; best_i = ci; }
        }

        // reload chosen code, exact stats
        const float* er = emb + (size_t)best_i * D;
        float ev[D / 32];
        float ee = 0.f, ze = 0.f;
#pragma unroll
        for (int j = 0; j < D / 32; j++) {
            ev[j] = er[lane + 32 * j];
            ee = fmaf(ev[j], ev[j], ee);
            ze = fmaf(zv[j], ev[j], ze);
        }
#pragma unroll
        for (int o = 16; o; o >>= 1) {
            ee += __shfl_xor_sync(0xffffffffu, ee, o);
            ze += __shfl_xor_sync(0xffffffffu, ze, o);
        }

        float ns_r = sqrtf(zz), nt_r = sqrtf(ee);
        float ns = fmaxf(ns_r, EPSF), nt = fmaxf(nt_r, EPSF);
        float dot_eu = zz / ns;
        float w2 = zz / (ns * ns) + ee / (nt * nt) + 2.f * ze / (ns * nt);
        float nw = fmaxf(sqrtf(w2), EPSF);
        float dot_ew = (dot_eu + ze / nt) / nw;
        float scale = nt_r / ns;
        float A = scale * (1.f - 2.f * dot_ew / (ns * nw));
        float B = scale * 2.f * (dot_eu - dot_ew / nw) / nt;

        float* orow = out + (size_t)row * D;
#pragma unroll
        for (int j = 0; j < D / 32; j++)
            orow[lane + 32 * j] = fmaf(A, zv[j], B * ev[j]);

        loss_w = zz + ee - 2.f * ze;
    }

    if (lane == 0) s_loss[warp] = loss_w;
    __syncthreads();
    if (threadIdx.x == 0) {
        float s = 0.f;
#pragma unroll
        for (int w = 0; w < 8; w++) s += s_loss[w];
        g_partial[blockIdx.x] = s;
    }
}

// ---------------- kernel 4: finalize scalar loss ----------------
__global__ void k_loss(float* __restrict__ out, int nparts, float inv_count, long long pos) {
    __shared__ float sm[256];
    float s = 0.f;
    for (int i = threadIdx.x; i < nparts; i += 256) s += g_partial[i];
    sm[threadIdx.x] = s;
    __syncthreads();
    for (int o = 128; o; o >>= 1) {
        if (threadIdx.x < o) sm[threadIdx.x] += sm[threadIdx.x + o];
        __syncthreads();
    }
    if (threadIdx.x == 0) out[pos] = 2.f * sm[0] * inv_count;
}

// ---------------- launch ----------------
extern "C" void kernel_launch(void* const* d_in, const int* in_sizes, int n_in,
                              void* d_out, int out_size) {
    const float* z   = (const float*)d_in[0];
    const float* emb = (const float*)d_in[1];
    float* out = (float*)d_out;

    int nrows  = in_sizes[0] / D;    // 32768
    int ncodes = in_sizes[1] / D;    // 8192

    int nz4 = nrows * D / 4, ne4 = ncodes * D / 4;
    k_split<<<4096, 256>>>((const float4*)z, (const float4*)emb, nz4, ne4);
    k_en2<<<(ncodes + 7) / 8, 256>>>(emb, ncodes);
    k_gemm<<<nrows / CTAM, 256>>>();
    k_rotate<<<nrows / 8, 256>>>(z, emb, out, nrows);

    long long zq_elems = (long long)nrows * D;
    long long loss_pos = (out_size > zq_elems) ? zq_elems : (long long)out_size - 1;
    k_loss<<<1, 256>>>(out, nrows / 8, 1.f / ((float)nrows * (float)D), loss_pos);
}

// round 7
// speedup vs baseline: 3.9988x; 1.4496x over previous
#include <cuda_runtime.h>
#include <cstdint>

#define D 768
#define NROWS 32768
#define NCODES 8192
#define EPSF 1e-6f

// ---- GEMM tiling ----
#define CTAM 256
#define CTAN 128
#define KCH 32                  // floats per k-chunk = 4 m16n8k8 steps
#define NK8 (KCH / 8)           // 4
#define NCHUNK (D / KCH)        // 24
#define NITER (NCODES / CTAN)   // 64
#define TOTALC (NITER * NCHUNK) // 1536 flat chunks
#define PADK 36                 // smem row stride (floats); (l4*36+lc) mod 32 all-distinct
#define A_BYTES (CTAM * PADK * 4)       // 36864
#define B_BYTES (CTAN * PADK * 4)       // 18432
#define STAGE_BYTES (A_BYTES + B_BYTES) // 55296
#define NSTG 3
#define SMEM_DYN (NSTG * STAGE_BYTES)   // 165888
#define NCAND 16                // 8 contributing threads per row x top-2 each

// ---------------- device scratch (no allocations allowed) ----------------
__device__ __align__(256) float g_Zh[NROWS * D];   // tf32-rounded z
__device__ __align__(256) float g_Eh[NCODES * D];  // tf32-rounded emb
__device__ float g_en2[NCODES];
__device__ int   g_cand[NROWS * NCAND];
__device__ float g_partial[NROWS / 8];

// ---------------- helpers ----------------
__device__ __forceinline__ uint32_t smem_u32(const void* p) {
    uint32_t a;
    asm("{ .reg .u64 t; cvta.to.shared.u64 t, %1; cvt.u32.u64 %0, t; }" : "=r"(a) : "l"(p));
    return a;
}
__device__ __forceinline__ void cp16(uint32_t dst, const float* src) {
    asm volatile("cp.async.cg.shared.global [%0], [%1], 16;" :: "r"(dst), "l"(src));
}
#define CP_COMMIT() asm volatile("cp.async.commit_group;")
#define CP_WAIT1()  asm volatile("cp.async.wait_group 1;")

__device__ __forceinline__ float tf32_rna(float x) {
    uint32_t r;
    asm("cvt.rna.tf32.f32 %0, %1;" : "=r"(r) : "f"(x));
    return __uint_as_float(r);
}
__device__ __forceinline__ void mma_tf32(float* c, const uint32_t* a, const uint32_t* b) {
    asm volatile(
        "mma.sync.aligned.m16n8k8.row.col.f32.tf32.tf32.f32 "
        "{%0,%1,%2,%3}, {%4,%5,%6,%7}, {%8,%9}, {%0,%1,%2,%3};"
        : "+f"(c[0]), "+f"(c[1]), "+f"(c[2]), "+f"(c[3])
        : "r"(a[0]), "r"(a[1]), "r"(a[2]), "r"(a[3]), "r"(b[0]), "r"(b[1]));
}

// ---------------- kernel 0: tf32 rounding of both operands ----------------
__global__ void k_split(const float4* __restrict__ z, const float4* __restrict__ e,
                        int nz4, int ne4) {
    float4* zh = (float4*)g_Zh;
    float4* eh = (float4*)g_Eh;
    for (int i = blockIdx.x * blockDim.x + threadIdx.x; i < nz4; i += gridDim.x * blockDim.x) {
        float4 v = z[i];
        float4 h;
        h.x = tf32_rna(v.x); h.y = tf32_rna(v.y);
        h.z = tf32_rna(v.z); h.w = tf32_rna(v.w);
        zh[i] = h;
        if (i < ne4) {
            float4 w = e[i];
            float4 he;
            he.x = tf32_rna(w.x); he.y = tf32_rna(w.y);
            he.z = tf32_rna(w.z); he.w = tf32_rna(w.w);
            eh[i] = he;
        }
    }
}

// ---------------- kernel 1: per-code squared norms (exact fp32) ----------------
__global__ void k_en2(const float* __restrict__ emb, int ncodes) {
    int code = blockIdx.x * 8 + (threadIdx.x >> 5);
    int lane = threadIdx.x & 31;
    if (code >= ncodes) return;
    const float* e = emb + (size_t)code * D;
    float s = 0.f;
#pragma unroll
    for (int j = 0; j < D / 32; j++) { float v = e[lane + 32 * j]; s = fmaf(v, v, s); }
#pragma unroll
    for (int o = 16; o; o >>= 1) s += __shfl_xor_sync(0xffffffffu, s, o);
    if (lane == 0) g_en2[code] = s;
}

// ---------------- kernel 2: tf32 mma.sync distance GEMM + top-2 candidates ----------------
// approx dist(m,n) = ||e_n||^2 - 2 * zh_m . eh_n   (||z||^2 constant per row -> dropped)
__global__ __launch_bounds__(256, 1)
void k_gemm() {
    extern __shared__ __align__(16) char smem[];
    const uint32_t sbase = smem_u32(smem);

    const int tid = threadIdx.x;
    const int wid = tid >> 5;
    const int lane = tid & 31;
    const int m0 = blockIdx.x * CTAM;
    const int wm = (wid & 3) * 64;   // warp M offset
    const int nh = wid >> 2;         // N-half 0/1
    const int wn = nh * 64;          // warp N offset
    const int l4 = lane >> 2;        // groupID 0..7
    const int lc = lane & 3;         // tid-in-group 0..3

    const float* gZ = g_Zh;
    const float* gE = g_Eh;

    const int ldrow = tid >> 3;      // 0..31 base row group? no: see idx scheme
    // candidate lists: 8 rows per thread (4 m-tiles x 2 halves), top-2 each
    float cv0[8], cv1[8];
    int   ci0[8], ci1[8];
#pragma unroll
    for (int r = 0; r < 8; r++) { cv0[r] = 3.4e38f; cv1[r] = 3.4e38f; ci0[r] = 0; ci1[r] = 0; }

    const int aoff = (wm + l4) * PADK + lc;
    const int boff = (wn + l4) * PADK + lc;

    // flat-chunk loader; ALWAYS commits exactly one group
    auto load_chunk = [&](int tc, int stage) {
        if (tc < TOTALC) {
            const int kc = (tc % NCHUNK) * KCH;
            const int n0 = (tc / NCHUNK) * CTAN;
            const uint32_t st = sbase + stage * STAGE_BYTES;
#pragma unroll
            for (int i = 0; i < 8; i++) {      // A: 2048 float4 / 256 thr
                int idx = tid + i * 256, row = idx >> 3, seg = idx & 7;
                cp16(st + row * (PADK * 4) + seg * 16,
                     gZ + (size_t)(m0 + row) * D + kc + seg * 4);
            }
#pragma unroll
            for (int i = 0; i < 4; i++) {      // B: 1024 float4
                int idx = tid + i * 256, row = idx >> 3, seg = idx & 7;
                cp16(st + A_BYTES + row * (PADK * 4) + seg * 16,
                     gE + (size_t)(n0 + row) * D + kc + seg * 4);
            }
        }
        CP_COMMIT();
    };

    // prologue: chunks 0,1 -> stages 0,1
    load_chunk(0, 0);
    load_chunk(1, 1);

    float acc[4][8][4];
#pragma unroll
    for (int mt = 0; mt < 4; mt++)
#pragma unroll
        for (int nt = 0; nt < 8; nt++)
#pragma unroll
            for (int q = 0; q < 4; q++) acc[mt][nt][q] = 0.f;

    for (int tc = 0; tc < TOTALC; tc++) {
        CP_WAIT1();                 // chunk tc landed (all but newest group done)
        __syncthreads();            // visible CTA-wide + prev stage consumers done

        load_chunk(tc + 2, (tc + 2) % NSTG);

        const float* As = (const float*)(smem + (tc % NSTG) * STAGE_BYTES);
        const float* Bs = (const float*)(smem + (tc % NSTG) * STAGE_BYTES + A_BYTES);
#pragma unroll
        for (int ks = 0; ks < NK8; ks++) {
            uint32_t af[4][4], bf[8][2];
#pragma unroll
            for (int mt = 0; mt < 4; mt++) {
                int b = aoff + mt * (16 * PADK) + ks * 8;
                af[mt][0] = __float_as_uint(As[b]);
                af[mt][1] = __float_as_uint(As[b + 8 * PADK]);
                af[mt][2] = __float_as_uint(As[b + 4]);
                af[mt][3] = __float_as_uint(As[b + 8 * PADK + 4]);
            }
#pragma unroll
            for (int nt = 0; nt < 8; nt++) {
                int b = boff + nt * (8 * PADK) + ks * 8;
                bf[nt][0] = __float_as_uint(Bs[b]);
                bf[nt][1] = __float_as_uint(Bs[b + 4]);
            }
#pragma unroll
            for (int mt = 0; mt < 4; mt++)
#pragma unroll
                for (int nt = 0; nt < 8; nt++)
                    mma_tf32(acc[mt][nt], af[mt], bf[nt]);
        }

        // ---- iteration boundary: fold 128-code tile into per-row top-2 ----
        if ((tc % NCHUNK) == NCHUNK - 1) {
            const int n0 = (tc / NCHUNK) * CTAN;
#pragma unroll
            for (int mt = 0; mt < 4; mt++) {
#pragma unroll
                for (int h = 0; h < 2; h++) {
                    const int r = mt * 2 + h;
#pragma unroll
                    for (int nt = 0; nt < 8; nt++) {
#pragma unroll
                        for (int q = 0; q < 2; q++) {
                            int nl = wn + nt * 8 + 2 * lc + q;
                            int n = n0 + nl;
                            float dist = fmaf(-2.f, acc[mt][nt][h * 2 + q], __ldg(&g_en2[n]));
                            if (dist < cv1[r]) {
                                if (dist < cv0[r]) {
                                    cv1[r] = cv0[r]; ci1[r] = ci0[r];
                                    cv0[r] = dist;   ci0[r] = n;
                                } else {
                                    cv1[r] = dist;   ci1[r] = n;
                                }
                            }
                            acc[mt][nt][h * 2 + q] = 0.f;   // reset for next tile
                        }
                    }
                }
            }
        }
    }

    // ---- write candidates: 16 per row; slot = n_half*8 + lc*2 (+1) -> no collisions ----
#pragma unroll
    for (int mt = 0; mt < 4; mt++) {
#pragma unroll
        for (int h = 0; h < 2; h++) {
            int r = mt * 2 + h;
            int grow = m0 + wm + mt * 16 + l4 + h * 8;
            int slot = nh * 8 + lc * 2;
            g_cand[(size_t)grow * NCAND + slot + 0] = ci0[r];
            g_cand[(size_t)grow * NCAND + slot + 1] = ci1[r];
        }
    }
}

// ---------------- kernel 3: exact rescore + rotation + loss partials ----------------
__global__ void k_rotate(const float* __restrict__ z, const float* __restrict__ emb,
                         float* __restrict__ out, int nrows) {
    __shared__ float s_loss[8];
    int warp = threadIdx.x >> 5;
    int lane = threadIdx.x & 31;
    int row = blockIdx.x * 8 + warp;
    float loss_w = 0.f;

    if (row < nrows) {
        const float* zr = z + (size_t)row * D;
        float zv[D / 32];
        float zz = 0.f;
#pragma unroll
        for (int j = 0; j < D / 32; j++) {
            zv[j] = zr[lane + 32 * j];
            zz = fmaf(zv[j], zv[j], zz);
        }
#pragma unroll
        for (int o = 16; o; o >>= 1) zz += __shfl_xor_sync(0xffffffffu, zz, o);

        // exact rescore of 16 candidates
        float best_key = 3.4e38f;
        int best_i = 0x7fffffff;
#pragma unroll
        for (int c = 0; c < NCAND; c++) {
            int ci = g_cand[(size_t)row * NCAND + c] & (NCODES - 1);  // fault guard
            const float* er = emb + (size_t)ci * D;
            float ze = 0.f;
#pragma unroll
            for (int j = 0; j < D / 32; j++) ze = fmaf(zv[j], er[lane + 32 * j], ze);
#pragma unroll
            for (int o = 16; o; o >>= 1) ze += __shfl_xor_sync(0xffffffffu, ze, o);
            float key = fmaf(-2.f, ze, g_en2[ci]);
            if (key < best_key || (key == best_key && ci < best_i)) { best_key = key; best_i = ci; }
        }

        // reload chosen code, exact stats
        const float* er = emb + (size_t)best_i * D;
        float ev[D / 32];
        float ee = 0.f, ze = 0.f;
#pragma unroll
        for (int j = 0; j < D / 32; j++) {
            ev[j] = er[lane + 32 * j];
            ee = fmaf(ev[j], ev[j], ee);
            ze = fmaf(zv[j], ev[j], ze);
        }
#pragma unroll
        for (int o = 16; o; o >>= 1) {
            ee += __shfl_xor_sync(0xffffffffu, ee, o);
            ze += __shfl_xor_sync(0xffffffffu, ze, o);
        }

        float ns_r = sqrtf(zz), nt_r = sqrtf(ee);
        float ns = fmaxf(ns_r, EPSF), nt = fmaxf(nt_r, EPSF);
        float dot_eu = zz / ns;
        float w2 = zz / (ns * ns) + ee / (nt * nt) + 2.f * ze / (ns * nt);
        float nw = fmaxf(sqrtf(w2), EPSF);
        float dot_ew = (dot_eu + ze / nt) / nw;
        float scale = nt_r / ns;
        float A = scale * (1.f - 2.f * dot_ew / (ns * nw));
        float B = scale * 2.f * (dot_eu - dot_ew / nw) / nt;

        float* orow = out + (size_t)row * D;
#pragma unroll
        for (int j = 0; j < D / 32; j++)
            orow[lane + 32 * j] = fmaf(A, zv[j], B * ev[j]);

        loss_w = zz + ee - 2.f * ze;
    }

    if (lane == 0) s_loss[warp] = loss_w;
    __syncthreads();
    if (threadIdx.x == 0) {
        float s = 0.f;
#pragma unroll
        for (int w = 0; w < 8; w++) s += s_loss[w];
        g_partial[blockIdx.x] = s;
    }
}

// ---------------- kernel 4: finalize scalar loss ----------------
__global__ void k_loss(float* __restrict__ out, int nparts, float inv_count, long long pos) {
    __shared__ float sm[256];
    float s = 0.f;
    for (int i = threadIdx.x; i < nparts; i += 256) s += g_partial[i];
    sm[threadIdx.x] = s;
    __syncthreads();
    for (int o = 128; o; o >>= 1) {
        if (threadIdx.x < o) sm[threadIdx.x] += sm[threadIdx.x + o];
        __syncthreads();
    }
    if (threadIdx.x == 0) out[pos] = 2.f * sm[0] * inv_count;
}

// ---------------- launch ----------------
extern "C" void kernel_launch(void* const* d_in, const int* in_sizes, int n_in,
                              void* d_out, int out_size) {
    const float* z   = (const float*)d_in[0];
    const float* emb = (const float*)d_in[1];
    float* out = (float*)d_out;

    int nrows  = in_sizes[0] / D;    // 32768
    int ncodes = in_sizes[1] / D;    // 8192

    cudaFuncSetAttribute(k_gemm, cudaFuncAttributeMaxDynamicSharedMemorySize, SMEM_DYN);

    int nz4 = nrows * D / 4, ne4 = ncodes * D / 4;
    k_split<<<4096, 256>>>((const float4*)z, (const float4*)emb, nz4, ne4);
    k_en2<<<(ncodes + 7) / 8, 256>>>(emb, ncodes);
    k_gemm<<<nrows / CTAM, 256, SMEM_DYN>>>();
    k_rotate<<<nrows / 8, 256>>>(z, emb, out, nrows);

    long long zq_elems = (long long)nrows * D;
    long long loss_pos = (out_size > zq_elems) ? zq_elems : (long long)out_size - 1;
    k_loss<<<1, 256>>>(out, nrows / 8, 1.f / ((float)nrows * (float)D), loss_pos);
}

// round 8
// speedup vs baseline: 7.3316x; 1.8335x over previous
#include <cuda_runtime.h>
#include <cuda_fp16.h>
#include <cstdint>

#define D 768
#define NROWS 32768
#define NCODES 8192
#define EPSF 1e-6f

// ---- GEMM tiling (fp16 operands, fp32 accumulate) ----
#define CTAM 256
#define CTAN 128
#define KCH 64                  // halfs per k-chunk = 4 m16n8k16 steps
#define NK16 (KCH / 16)         // 4
#define NCHUNK (D / KCH)        // 12
#define NITER (NCODES / CTAN)   // 64
#define TOTALC (NITER * NCHUNK) // 768 flat chunks
#define PADK 36                 // row stride in half2 units; (l4*36+lc) mod 32 all-distinct
#define A_BYTES (CTAM * PADK * 4)       // 36864
#define B_BYTES (CTAN * PADK * 4)       // 18432
#define STAGE_BYTES (A_BYTES + B_BYTES) // 55296
#define NSTG 3
#define SMEM_DYN (NSTG * STAGE_BYTES)   // 165888
#define NCAND 16                // 8 contributing threads per row x top-2 each

// ---------------- device scratch (no allocations allowed) ----------------
__device__ __align__(256) __half g_Zh[NROWS * D];   // fp16-rounded z
__device__ __align__(256) __half g_Eh[NCODES * D];  // fp16-rounded emb
__device__ float g_en2[NCODES];
__device__ int   g_cand[NROWS * NCAND];
__device__ float g_partial[NROWS / 8];

// ---------------- helpers ----------------
__device__ __forceinline__ uint32_t smem_u32(const void* p) {
    uint32_t a;
    asm("{ .reg .u64 t; cvta.to.shared.u64 t, %1; cvt.u32.u64 %0, t; }" : "=r"(a) : "l"(p));
    return a;
}
__device__ __forceinline__ void cp16(uint32_t dst, const void* src) {
    asm volatile("cp.async.cg.shared.global [%0], [%1], 16;" :: "r"(dst), "l"(src));
}
#define CP_COMMIT() asm volatile("cp.async.commit_group;")
#define CP_WAIT1()  asm volatile("cp.async.wait_group 1;")

__device__ __forceinline__ void mma_f16(float* c, const uint32_t* a, const uint32_t* b) {
    asm volatile(
        "mma.sync.aligned.m16n8k16.row.col.f32.f16.f16.f32 "
        "{%0,%1,%2,%3}, {%4,%5,%6,%7}, {%8,%9}, {%0,%1,%2,%3};"
        : "+f"(c[0]), "+f"(c[1]), "+f"(c[2]), "+f"(c[3])
        : "r"(a[0]), "r"(a[1]), "r"(a[2]), "r"(a[3]), "r"(b[0]), "r"(b[1]));
}

// ---------------- kernel 0: fp16 rounding of both operands ----------------
__global__ void k_split(const float4* __restrict__ z, const float4* __restrict__ e,
                        int nz4, int ne4) {
    __half2* zh = (__half2*)g_Zh;
    __half2* eh = (__half2*)g_Eh;
    for (int i = blockIdx.x * blockDim.x + threadIdx.x; i < nz4; i += gridDim.x * blockDim.x) {
        float4 v = z[i];
        zh[2 * i]     = __floats2half2_rn(v.x, v.y);
        zh[2 * i + 1] = __floats2half2_rn(v.z, v.w);
        if (i < ne4) {
            float4 w = e[i];
            eh[2 * i]     = __floats2half2_rn(w.x, w.y);
            eh[2 * i + 1] = __floats2half2_rn(w.z, w.w);
        }
    }
}

// ---------------- kernel 1: per-code squared norms (exact fp32) ----------------
__global__ void k_en2(const float* __restrict__ emb, int ncodes) {
    int code = blockIdx.x * 8 + (threadIdx.x >> 5);
    int lane = threadIdx.x & 31;
    if (code >= ncodes) return;
    const float* e = emb + (size_t)code * D;
    float s = 0.f;
#pragma unroll
    for (int j = 0; j < D / 32; j++) { float v = e[lane + 32 * j]; s = fmaf(v, v, s); }
#pragma unroll
    for (int o = 16; o; o >>= 1) s += __shfl_xor_sync(0xffffffffu, s, o);
    if (lane == 0) g_en2[code] = s;
}

// ---------------- kernel 2: fp16 mma.sync distance GEMM + top-2 candidates ----------------
// approx dist(m,n) = ||e_n||^2 - 2 * zh_m . eh_n   (||z||^2 constant per row -> dropped)
__global__ __launch_bounds__(256, 1)
void k_gemm() {
    extern __shared__ __align__(16) char smem[];
    const uint32_t sbase = smem_u32(smem);

    const int tid = threadIdx.x;
    const int wid = tid >> 5;
    const int lane = tid & 31;
    const int m0 = blockIdx.x * CTAM;
    const int wm = (wid & 3) * 64;   // warp M offset
    const int nh = wid >> 2;         // N-half 0/1
    const int wn = nh * 64;          // warp N offset
    const int l4 = lane >> 2;        // groupID 0..7
    const int lc = lane & 3;         // tid-in-group 0..3

    const __half* gZ = g_Zh;
    const __half* gE = g_Eh;

    // candidate lists: 8 rows per thread (4 m-tiles x 2 halves), top-2 each
    float cv0[8], cv1[8];
    int   ci0[8], ci1[8];
#pragma unroll
    for (int r = 0; r < 8; r++) { cv0[r] = 3.4e38f; cv1[r] = 3.4e38f; ci0[r] = 0; ci1[r] = 0; }

    // fragment base offsets (half2 units)
    const int aoff = (wm + l4) * PADK + lc;
    const int boff = (wn + l4) * PADK + lc;

    // flat-chunk loader; ALWAYS commits exactly one group
    auto load_chunk = [&](int tc, int stage) {
        if (tc < TOTALC) {
            const int kc = (tc % NCHUNK) * KCH;     // in halfs
            const int n0 = (tc / NCHUNK) * CTAN;
            const uint32_t st = sbase + stage * STAGE_BYTES;
#pragma unroll
            for (int i = 0; i < 8; i++) {      // A: 256 rows x 128B = 2048 x16B
                int idx = tid + i * 256, row = idx >> 3, seg = idx & 7;
                cp16(st + row * (PADK * 4) + seg * 16,
                     gZ + (size_t)(m0 + row) * D + kc + seg * 8);
            }
#pragma unroll
            for (int i = 0; i < 4; i++) {      // B: 128 rows x 128B = 1024 x16B
                int idx = tid + i * 256, row = idx >> 3, seg = idx & 7;
                cp16(st + A_BYTES + row * (PADK * 4) + seg * 16,
                     gE + (size_t)(n0 + row) * D + kc + seg * 8);
            }
        }
        CP_COMMIT();
    };

    // prologue: chunks 0,1 -> stages 0,1
    load_chunk(0, 0);
    load_chunk(1, 1);

    float acc[4][8][4];
#pragma unroll
    for (int mt = 0; mt < 4; mt++)
#pragma unroll
        for (int nt = 0; nt < 8; nt++)
#pragma unroll
            for (int q = 0; q < 4; q++) acc[mt][nt][q] = 0.f;

    for (int tc = 0; tc < TOTALC; tc++) {
        CP_WAIT1();                 // chunk tc landed (all but newest group done)
        __syncthreads();            // visible CTA-wide + prev stage consumers done

        load_chunk(tc + 2, (tc + 2) % NSTG);

        const uint32_t* As = (const uint32_t*)(smem + (tc % NSTG) * STAGE_BYTES);
        const uint32_t* Bs = (const uint32_t*)(smem + (tc % NSTG) * STAGE_BYTES + A_BYTES);
#pragma unroll
        for (int ks = 0; ks < NK16; ks++) {
            uint32_t af[4][4], bf[8][2];
#pragma unroll
            for (int mt = 0; mt < 4; mt++) {
                int b = aoff + mt * (16 * PADK) + ks * 8;
                af[mt][0] = As[b];                 // (row g,    k 2lc..2lc+1)
                af[mt][1] = As[b + 8 * PADK];      // (row g+8,  same k)
                af[mt][2] = As[b + 4];             // (row g,    k+8)
                af[mt][3] = As[b + 8 * PADK + 4];  // (row g+8,  k+8)
            }
#pragma unroll
            for (int nt = 0; nt < 8; nt++) {
                int b = boff + nt * (8 * PADK) + ks * 8;
                bf[nt][0] = Bs[b];                 // (col g, k 2lc..2lc+1)
                bf[nt][1] = Bs[b + 4];             // (col g, k+8)
            }
#pragma unroll
            for (int mt = 0; mt < 4; mt++)
#pragma unroll
                for (int nt = 0; nt < 8; nt++)
                    mma_f16(acc[mt][nt], af[mt], bf[nt]);
        }

        // ---- iteration boundary: fold 128-code tile into per-row top-2 ----
        if ((tc % NCHUNK) == NCHUNK - 1) {
            const int n0 = (tc / NCHUNK) * CTAN;
#pragma unroll
            for (int mt = 0; mt < 4; mt++) {
#pragma unroll
                for (int h = 0; h < 2; h++) {
                    const int r = mt * 2 + h;
#pragma unroll
                    for (int nt = 0; nt < 8; nt++) {
#pragma unroll
                        for (int q = 0; q < 2; q++) {
                            int nl = wn + nt * 8 + 2 * lc + q;
                            int n = n0 + nl;
                            float dist = fmaf(-2.f, acc[mt][nt][h * 2 + q], __ldg(&g_en2[n]));
                            if (dist < cv1[r]) {
                                if (dist < cv0[r]) {
                                    cv1[r] = cv0[r]; ci1[r] = ci0[r];
                                    cv0[r] = dist;   ci0[r] = n;
                                } else {
                                    cv1[r] = dist;   ci1[r] = n;
                                }
                            }
                            acc[mt][nt][h * 2 + q] = 0.f;   // reset for next tile
                        }
                    }
                }
            }
        }
    }

    // ---- write candidates: 16 per row; slot = n_half*8 + lc*2 (+1) -> no collisions ----
#pragma unroll
    for (int mt = 0; mt < 4; mt++) {
#pragma unroll
        for (int h = 0; h < 2; h++) {
            int r = mt * 2 + h;
            int grow = m0 + wm + mt * 16 + l4 + h * 8;
            int slot = nh * 8 + lc * 2;
            g_cand[(size_t)grow * NCAND + slot + 0] = ci0[r];
            g_cand[(size_t)grow * NCAND + slot + 1] = ci1[r];
        }
    }
}

// ---------------- kernel 3: exact rescore + rotation + loss partials ----------------
__global__ void k_rotate(const float* __restrict__ z, const float* __restrict__ emb,
                         float* __restrict__ out, int nrows) {
    __shared__ float s_loss[8];
    int warp = threadIdx.x >> 5;
    int lane = threadIdx.x & 31;
    int row = blockIdx.x * 8 + warp;
    float loss_w = 0.f;

    if (row < nrows) {
        const float* zr = z + (size_t)row * D;
        float zv[D / 32];
        float zz = 0.f;
#pragma unroll
        for (int j = 0; j < D / 32; j++) {
            zv[j] = zr[lane + 32 * j];
            zz = fmaf(zv[j], zv[j], zz);
        }
#pragma unroll
        for (int o = 16; o; o >>= 1) zz += __shfl_xor_sync(0xffffffffu, zz, o);

        // exact rescore of 16 candidates
        float best_key = 3.4e38f;
        int best_i = 0x7fffffff;
#pragma unroll
        for (int c = 0; c < NCAND; c++) {
            int ci = g_cand[(size_t)row * NCAND + c] & (NCODES - 1);  // fault guard
            const float* er = emb + (size_t)ci * D;
            float ze = 0.f;
#pragma unroll
            for (int j = 0; j < D / 32; j++) ze = fmaf(zv[j], er[lane + 32 * j], ze);
#pragma unroll
            for (int o = 16; o; o >>= 1) ze += __shfl_xor_sync(0xffffffffu, ze, o);
            float key = fmaf(-2.f, ze, g_en2[ci]);
            if (key < best_key || (key == best_key && ci < best_i)) { best_key = key; best_i = ci; }
        }

        // reload chosen code, exact stats
        const float* er = emb + (size_t)best_i * D;
        float ev[D / 32];
        float ee = 0.f, ze = 0.f;
#pragma unroll
        for (int j = 0; j < D / 32; j++) {
            ev[j] = er[lane + 32 * j];
            ee = fmaf(ev[j], ev[j], ee);
            ze = fmaf(zv[j], ev[j], ze);
        }
#pragma unroll
        for (int o = 16; o; o >>= 1) {
            ee += __shfl_xor_sync(0xffffffffu, ee, o);
            ze += __shfl_xor_sync(0xffffffffu, ze, o);
        }

        float ns_r = sqrtf(zz), nt_r = sqrtf(ee);
        float ns = fmaxf(ns_r, EPSF), nt = fmaxf(nt_r, EPSF);
        float dot_eu = zz / ns;
        float w2 = zz / (ns * ns) + ee / (nt * nt) + 2.f * ze / (ns * nt);
        float nw = fmaxf(sqrtf(w2), EPSF);
        float dot_ew = (dot_eu + ze / nt) / nw;
        float scale = nt_r / ns;
        float A = scale * (1.f - 2.f * dot_ew / (ns * nw));
        float B = scale * 2.f * (dot_eu - dot_ew / nw) / nt;

        float* orow = out + (size_t)row * D;
#pragma unroll
        for (int j = 0; j < D / 32; j++)
            orow[lane + 32 * j] = fmaf(A, zv[j], B * ev[j]);

        loss_w = zz + ee - 2.f * ze;
    }

    if (lane == 0) s_loss[warp] = loss_w;
    __syncthreads();
    if (threadIdx.x == 0) {
        float s = 0.f;
#pragma unroll
        for (int w = 0; w < 8; w++) s += s_loss[w];
        g_partial[blockIdx.x] = s;
    }
}

// ---------------- kernel 4: finalize scalar loss ----------------
__global__ void k_loss(float* __restrict__ out, int nparts, float inv_count, long long pos) {
    __shared__ float sm[256];
    float s = 0.f;
    for (int i = threadIdx.x; i < nparts; i += 256) s += g_partial[i];
    sm[threadIdx.x] = s;
    __syncthreads();
    for (int o = 128; o; o >>= 1) {
        if (threadIdx.x < o) sm[threadIdx.x] += sm[threadIdx.x + o];
        __syncthreads();
    }
    if (threadIdx.x == 0) out[pos] = 2.f * sm[0] * inv_count;
}

// ---------------- launch ----------------
extern "C" void kernel_launch(void* const* d_in, const int* in_sizes, int n_in,
                              void* d_out, int out_size) {
    const float* z   = (const float*)d_in[0];
    const float* emb = (const float*)d_in[1];
    float* out = (float*)d_out;

    int nrows  = in_sizes[0] / D;    // 32768
    int ncodes = in_sizes[1] / D;    // 8192

    cudaFuncSetAttribute(k_gemm, cudaFuncAttributeMaxDynamicSharedMemorySize, SMEM_DYN);

    int nz4 = nrows * D / 4, ne4 = ncodes * D / 4;
    k_split<<<4096, 256>>>((const float4*)z, (const float4*)emb, nz4, ne4);
    k_en2<<<(ncodes + 7) / 8, 256>>>(emb, ncodes);
    k_gemm<<<nrows / CTAM, 256, SMEM_DYN>>>();
    k_rotate<<<nrows / 8, 256>>>(z, emb, out, nrows);

    long long zq_elems = (long long)nrows * D;
    long long loss_pos = (out_size > zq_elems) ? zq_elems : (long long)out_size - 1;
    k_loss<<<1, 256>>>(out, nrows / 8, 1.f / ((float)nrows * (float)D), loss_pos);
}